// round 15
// baseline (speedup 1.0000x reference)
#include <cuda_runtime.h>

#define NN 50000
#define EE 1600000
#define BBB 512

// ---------------- device scratch (static; no allocation) ----------------
// ZERO-INVARIANT: g_hist/g_cur zero at load; restored to zero in k_node L0.
__device__ float g_h[NN * 64];
__device__ float g_x[NN * 3];
__device__ float g_P1[NN * 64];
__device__ float g_P2[NN * 64];
__device__ float g_magg[NN * 64];
__device__ float g_dx[NN * 3];
__device__ int   g_hist[NN];
__device__ int   g_offs[NN + 1];
__device__ int   g_cur[NN];
__device__ int   g_col[EE];
__device__ int   g_row[EE];
__device__ float g_qsum[BBB];
__device__ float g_qx[BBB * 3];
__device__ float g_xsum[BBB * 3];
__device__ float g_cnt[BBB];

typedef unsigned long long u64;

// ---------------- packed f32x2 helpers ----------------------------------
__device__ __forceinline__ u64 fma2(u64 a, u64 b, u64 c) {
    u64 d;
    asm("fma.rn.f32x2 %0, %1, %2, %3;" : "=l"(d) : "l"(a), "l"(b), "l"(c));
    return d;
}
__device__ __forceinline__ u64 add2(u64 a, u64 b) {
    u64 d;
    asm("add.rn.f32x2 %0, %1, %2;" : "=l"(d) : "l"(a), "l"(b));
    return d;
}
__device__ __forceinline__ u64 pack2(float v) {
    u64 d;
    asm("mov.b64 %0, {%1, %1};" : "=l"(d) : "f"(v));
    return d;
}
__device__ __forceinline__ u64 packxy(float x, float y) {
    u64 d;
    asm("mov.b64 %0, {%1, %2};" : "=l"(d) : "f"(x), "f"(y));
    return d;
}
__device__ __forceinline__ float2 unpack(u64 v) {
    float2 f;
    asm("mov.b64 {%0, %1}, %2;" : "=f"(f.x), "=f"(f.y) : "l"(v));
    return f;
}

__device__ __forceinline__ float silu(float v) {
    float e = __expf(-v);
    return __fdividef(v, 1.0f + e);
}

// ---------------- init + edge histogram (zero-invariant g_hist) ----------
__global__ void k_inithist(const int* __restrict__ z, const float* __restrict__ pos,
                           const float* __restrict__ emb, const int* __restrict__ ei,
                           int N, int B, int E) {
    int tid = blockIdx.x * blockDim.x + threadIdx.x;
    if (tid < N * 64) {
        int n = tid >> 6, k = tid & 63;
        g_h[tid] = emb[z[n] * 64 + k];
    }
    if (tid < E) atomicAdd(&g_hist[ei[tid]], 1);
    if (tid < N * 3) g_x[tid] = pos[tid];
    if (tid < B) { g_qsum[tid] = 0.f; g_cnt[tid] = 0.f; }
    if (tid < B * 3) { g_qx[tid] = 0.f; g_xsum[tid] = 0.f; }
}

__global__ void k_scan(int N) {
    __shared__ int ss[1024];
    int tid = threadIdx.x;
    int ch = (N + 1023) / 1024;
    int base = tid * ch;
    int s = 0;
    for (int i = 0; i < ch; i++) {
        int idx = base + i;
        if (idx < N) s += g_hist[idx];
    }
    ss[tid] = s;
    __syncthreads();
    for (int off = 1; off < 1024; off <<= 1) {
        int v = (tid >= off) ? ss[tid - off] : 0;
        __syncthreads();
        ss[tid] += v;
        __syncthreads();
    }
    int run = (tid == 0) ? 0 : ss[tid - 1];
    for (int i = 0; i < ch; i++) {
        int idx = base + i;
        if (idx < N) { g_offs[idx] = run; run += g_hist[idx]; }
    }
    if (tid == 1023) g_offs[N] = ss[1023];
}

// ---------------- scatter + layer-0 proj fused ---------------------------
__device__ __forceinline__ void proj_body(const float* __restrict__ eW1,
                                          const float* __restrict__ eb1,
                                          int N, int bid, int pgrid, int tid) {
    __shared__ u64 sA[64 * 32];
    __shared__ u64 sB[64 * 32];
    __shared__ u64 sb1[32];
    __shared__ __align__(16) float hb[8][64];
    const float* W1a = eW1;
    const float* W1b = eW1 + 64 * 64;
    for (int idx = tid; idx < 2048; idx += 256) {
        int i = idx >> 5, j2 = idx & 31;
        sA[idx] = packxy(W1a[i * 64 + 2 * j2], W1a[i * 64 + 2 * j2 + 1]);
        sB[idx] = packxy(W1b[i * 64 + 2 * j2], W1b[i * 64 + 2 * j2 + 1]);
    }
    if (tid < 32) sb1[tid] = packxy(eb1[2 * tid], eb1[2 * tid + 1]);
    __syncthreads();
    int wid = tid >> 5, lane = tid & 31;
    for (int n = bid * 8 + wid; n < N; n += pgrid * 8) {
        __syncwarp();
        hb[wid][lane]      = g_h[n * 64 + lane];
        hb[wid][lane + 32] = g_h[n * 64 + lane + 32];
        __syncwarp();
        u64 a1a = sb1[lane], a1b = 0ull;
        u64 a2a = 0ull, a2b = 0ull;
        #pragma unroll 8
        for (int i = 0; i < 64; i += 2) {
            u64 v0 = pack2(hb[wid][i]);
            u64 v1 = pack2(hb[wid][i + 1]);
            a1a = fma2(v0, sA[i * 32 + lane], a1a);
            a2a = fma2(v0, sB[i * 32 + lane], a2a);
            a1b = fma2(v1, sA[(i + 1) * 32 + lane], a1b);
            a2b = fma2(v1, sB[(i + 1) * 32 + lane], a2b);
        }
        ((float2*)(g_P1 + n * 64))[lane] = unpack(add2(a1a, a1b));
        ((float2*)(g_P2 + n * 64))[lane] = unpack(add2(a2a, a2b));
        ((float2*)(g_magg + n * 64))[lane] = make_float2(0.f, 0.f);
        if (lane < 3) g_dx[n * 3 + lane] = 0.f;
    }
}

__global__ __launch_bounds__(256) void k_scatprj(const int* __restrict__ ei, int E,
                                                 const float* __restrict__ eW1,
                                                 const float* __restrict__ eb1,
                                                 int N, int scatBlocks) {
    if ((int)blockIdx.x < scatBlocks) {
        int e = blockIdx.x * 256 + threadIdx.x;
        if (e < E) {
            int r = ei[e];
            int idx = g_offs[r] + atomicAdd(&g_cur[r], 1);
            g_col[idx] = ei[E + e];
            g_row[idx] = r;
        }
        return;
    }
    proj_body(eW1, eb1, N, (int)blockIdx.x - scatBlocks,
              (int)gridDim.x - scatBlocks, threadIdx.x);
}

__global__ __launch_bounds__(256) void k_proj(const float* __restrict__ eW1,
                                              const float* __restrict__ eb1, int N) {
    proj_body(eW1, eb1, N, (int)blockIdx.x, (int)gridDim.x, threadIdx.x);
}

// ---------------- edge kernel: quad, E=3 sets x C=16 channels ------------
// Quad of 4 warps handles 96 edges/pass (sets 0..2 of 32). Warp wq computes
// output quarter [wq*16, wq*16+16) for ALL 3 sets (acc 3x8 u64 = 48 regs);
// weight broadcasts amortized over 3 sets -> wf/edge: 32/3 + 128/16 ~ 18.7.
// Pass: precompute rows/cols/d2s (warps 0-2) -> bar -> per k-chunk: stage +
// phase1 (6 tasks on 4 warps) -> bar -> GEMV -> bar -> epilogue (2 rounds,
// ms overlays dead tiles) -> bar -> dx (warps 0-2).
// Per-quad smem: 4x4352 tile/ms + rows 384 + cols 384 + d2s 384 + cds 1536
// = 20096. Block: 16384 + 2*20096 = 56576 -> 3 blocks/SM, 24 warps.
__global__ __launch_bounds__(256, 3) void k_edge(const float* __restrict__ eW1,
                                                 const float* __restrict__ eW2,
                                                 const float* __restrict__ eb2,
                                                 const float* __restrict__ cW,
                                                 const float* __restrict__ cb, int E) {
    extern __shared__ __align__(16) char dyn[];
    u64* sW2 = (u64*)dyn;
    __shared__ u64 sb2[32];
    __shared__ __align__(16) float swd[64];
    __shared__ float scw[64];
    __shared__ float scb;
    int tid = threadIdx.x;
    for (int idx = tid; idx < 2048; idx += 256) {
        int i = idx >> 5, j2 = idx & 31;
        sW2[idx] = packxy(eW2[i * 64 + 2 * j2], eW2[i * 64 + 2 * j2 + 1]);
    }
    if (tid < 64) { swd[tid] = eW1[128 * 64 + tid]; scw[tid] = cW[tid]; }
    if (tid < 32) sb2[tid] = packxy(eb2[2 * tid], eb2[2 * tid + 1]);
    if (tid == 0) scb = cb[0];
    __syncthreads();
    int wid = tid >> 5, lane = tid & 31;
    int quad = wid >> 2, wq = wid & 3;
    char* qb = dyn + 16384 + quad * 20096;
    float4* t0 = (float4*)qb;
    float4* t1 = (float4*)(qb + 4352);
    float4* t2 = (float4*)(qb + 8704);
    float*  msW = (float*)(qb + wq * 4352);     // epilogue overlay (2x528 fl)
    int*   rows = (int*)(qb + 17408);           // [3][32]
    int*   cols = (int*)(qb + 17792);           // [3][32]
    float* d2s  = (float*)(qb + 18176);         // [3][32]
    float* cds  = (float*)(qb + 18560);         // [3 sets][4 warps][32]
    int barid = quad + 1;
    float cbv = scb;
    int ln7 = lane & 7;
    int quadg = blockIdx.x * 2 + quad;
    int nquad = gridDim.x * 2;
    for (int base = quadg * 96; base < E; base += nquad * 96) {
        // ---- precompute own set (warps 0..2) ----
        int r = 0, c = 0;
        float r0 = 0.f, r1 = 0.f, r2 = 0.f;
        bool v = false;
        if (wq < 3) {
            int e = base + wq * 32 + lane;
            v = (e < E);
            int ee = v ? e : (E - 1);
            r = g_row[ee];
            c = g_col[ee];
            rows[wq * 32 + lane] = r;
            cols[wq * 32 + lane] = c;
            r0 = g_x[r * 3]     - g_x[c * 3];
            r1 = g_x[r * 3 + 1] - g_x[c * 3 + 1];
            r2 = g_x[r * 3 + 2] - g_x[c * 3 + 2];
            d2s[wq * 32 + lane] = r0 * r0 + r1 * r1 + r2 * r2;
        }
        asm volatile("bar.sync %0, %1;" :: "r"(barid), "r"(128) : "memory");
        u64 acc0[8], acc1[8], acc2[8];
        #pragma unroll
        for (int j = 0; j < 8; j++) {
            acc0[j] = sb2[wq * 8 + j];
            acc1[j] = acc0[j];
            acc2[j] = acc0[j];
        }
        #pragma unroll
        for (int chunk = 0; chunk < 2; chunk++) {
            // ---- stage + phase1: tasks (set, node-half) on 4 warps ----
            for (int t = wq; t < 6; t += 4) {
                int st = t >> 1, nh = t & 1;
                float4* ts = (st == 0) ? t0 : (st == 1) ? t1 : t2;
                #pragma unroll
                for (int i = 0; i < 4; i++) {
                    int node = nh * 16 + i * 4 + (lane >> 3);
                    int cc = cols[st * 32 + node];
                    float4 val = ((const float4*)(g_P2 + cc * 64))[chunk * 8 + ln7];
                    ts[node * 8 + (ln7 ^ (node & 7))] = val;
                }
                __syncwarp();
                #pragma unroll
                for (int i = 0; i < 4; i++) {
                    int node = nh * 16 + i * 4 + (lane >> 3);
                    bool vv = (base + st * 32 + node) < E;
                    int rr = rows[st * 32 + node];
                    float dd = d2s[st * 32 + node];
                    int slot = node * 8 + (ln7 ^ (node & 7));
                    float4 cv = ts[slot];
                    float4 tb = ((const float4*)(g_P1 + rr * 64))[chunk * 8 + ln7];
                    float4 wd = ((const float4*)swd)[chunk * 8 + ln7];
                    float4 u;
                    u.x = vv ? silu(tb.x + cv.x + dd * wd.x) : 0.f;
                    u.y = vv ? silu(tb.y + cv.y + dd * wd.y) : 0.f;
                    u.z = vv ? silu(tb.z + cv.z + dd * wd.z) : 0.f;
                    u.w = vv ? silu(tb.w + cv.w + dd * wd.w) : 0.f;
                    ts[slot] = u;
                }
                __syncwarp();
            }
            asm volatile("bar.sync %0, %1;" :: "r"(barid), "r"(128) : "memory");
            // ---- GEMV chunk: 16 channels (quarter), 3 sets ----
            #pragma unroll
            for (int qq = 0; qq < 8; qq++) {
                int q = chunk * 8 + qq;
                float4 x0 = t0[lane * 8 + (qq ^ ln7)];
                float4 x1 = t1[lane * 8 + (qq ^ ln7)];
                float4 x2 = t2[lane * 8 + (qq ^ ln7)];
                u64 ax[3][4];
                ax[0][0] = pack2(x0.x); ax[0][1] = pack2(x0.y);
                ax[0][2] = pack2(x0.z); ax[0][3] = pack2(x0.w);
                ax[1][0] = pack2(x1.x); ax[1][1] = pack2(x1.y);
                ax[1][2] = pack2(x1.z); ax[1][3] = pack2(x1.w);
                ax[2][0] = pack2(x2.x); ax[2][1] = pack2(x2.y);
                ax[2][2] = pack2(x2.z); ax[2][3] = pack2(x2.w);
                const ulonglong2* wp = (const ulonglong2*)(sW2 + (q * 4) * 32 + wq * 8);
                #pragma unroll
                for (int i = 0; i < 4; i++) {
                    ulonglong2 b0 = wp[i * 16 + 0];
                    ulonglong2 b1 = wp[i * 16 + 1];
                    ulonglong2 b2 = wp[i * 16 + 2];
                    ulonglong2 b3 = wp[i * 16 + 3];
                    u64 a0 = ax[0][i], a1 = ax[1][i], a2 = ax[2][i];
                    acc0[0] = fma2(a0, b0.x, acc0[0]);
                    acc1[0] = fma2(a1, b0.x, acc1[0]);
                    acc2[0] = fma2(a2, b0.x, acc2[0]);
                    acc0[1] = fma2(a0, b0.y, acc0[1]);
                    acc1[1] = fma2(a1, b0.y, acc1[1]);
                    acc2[1] = fma2(a2, b0.y, acc2[1]);
                    acc0[2] = fma2(a0, b1.x, acc0[2]);
                    acc1[2] = fma2(a1, b1.x, acc1[2]);
                    acc2[2] = fma2(a2, b1.x, acc2[2]);
                    acc0[3] = fma2(a0, b1.y, acc0[3]);
                    acc1[3] = fma2(a1, b1.y, acc1[3]);
                    acc2[3] = fma2(a2, b1.y, acc2[3]);
                    acc0[4] = fma2(a0, b2.x, acc0[4]);
                    acc1[4] = fma2(a1, b2.x, acc1[4]);
                    acc2[4] = fma2(a2, b2.x, acc2[4]);
                    acc0[5] = fma2(a0, b2.y, acc0[5]);
                    acc1[5] = fma2(a1, b2.y, acc1[5]);
                    acc2[5] = fma2(a2, b2.y, acc2[5]);
                    acc0[6] = fma2(a0, b3.x, acc0[6]);
                    acc1[6] = fma2(a1, b3.x, acc1[6]);
                    acc2[6] = fma2(a2, b3.x, acc2[6]);
                    acc0[7] = fma2(a0, b3.y, acc0[7]);
                    acc1[7] = fma2(a1, b3.y, acc1[7]);
                    acc2[7] = fma2(a2, b3.y, acc2[7]);
                }
            }
            asm volatile("bar.sync %0, %1;" :: "r"(barid), "r"(128) : "memory");
        }
        // ---- epilogue round 0: sets 0,1 ----
        #pragma unroll
        for (int ss = 0; ss < 2; ss++) {
            bool vs = (base + ss * 32 + lane) < E;
            float cd = 0.f;
            #pragma unroll
            for (int j = 0; j < 8; j++) {
                u64 a = ss ? acc1[j] : acc0[j];
                float2 m2 = unpack(a);
                float m0 = vs ? silu(m2.x) : 0.f;
                float m1 = vs ? silu(m2.y) : 0.f;
                cd += m0 * scw[wq * 16 + 2 * j] + m1 * scw[wq * 16 + 2 * j + 1];
                msW[ss * 528 + (2 * j) * 33 + lane]     = m0;
                msW[ss * 528 + (2 * j + 1) * 33 + lane] = m1;
            }
            cds[(ss * 4 + wq) * 32 + lane] = cd;
        }
        __syncwarp();
        {
            int sEl = lane >> 4;
            int chL = lane & 15;
            const float* msS = msW + sEl * 528;
            const int* rowsS = rows + sEl * 32;
            float sum = 0.f;
            #pragma unroll
            for (int e2 = 0; e2 < 32; e2++) {
                sum += msS[chL * 33 + e2];
                int rr = rowsS[e2];
                int rnx = (e2 < 31) ? rowsS[e2 + 1] : -1;
                if (rr != rnx) {
                    atomicAdd(&g_magg[rr * 64 + wq * 16 + chL], sum);
                    sum = 0.f;
                }
            }
        }
        __syncwarp();
        // ---- epilogue round 1: set 2 ----
        {
            bool vs = (base + 2 * 32 + lane) < E;
            float cd = 0.f;
            #pragma unroll
            for (int j = 0; j < 8; j++) {
                float2 m2 = unpack(acc2[j]);
                float m0 = vs ? silu(m2.x) : 0.f;
                float m1 = vs ? silu(m2.y) : 0.f;
                cd += m0 * scw[wq * 16 + 2 * j] + m1 * scw[wq * 16 + 2 * j + 1];
                msW[(2 * j) * 33 + lane]     = m0;
                msW[(2 * j + 1) * 33 + lane] = m1;
            }
            cds[(2 * 4 + wq) * 32 + lane] = cd;
        }
        __syncwarp();
        if (lane < 16) {
            int chL = lane;
            const int* rowsS = rows + 2 * 32;
            float sum = 0.f;
            #pragma unroll
            for (int e2 = 0; e2 < 32; e2++) {
                sum += msW[chL * 33 + e2];
                int rr = rowsS[e2];
                int rnx = (e2 < 31) ? rowsS[e2 + 1] : -1;
                if (rr != rnx) {
                    atomicAdd(&g_magg[rr * 64 + wq * 16 + chL], sum);
                    sum = 0.f;
                }
            }
        }
        asm volatile("bar.sync %0, %1;" :: "r"(barid), "r"(128) : "memory");
        // ---- coef + dx (warps 0..2 own their set) ----
        if (wq < 3 && v) {
            float cd = cbv + cds[(wq * 4 + 0) * 32 + lane] + cds[(wq * 4 + 1) * 32 + lane]
                           + cds[(wq * 4 + 2) * 32 + lane] + cds[(wq * 4 + 3) * 32 + lane];
            float coef = tanhf(cd);
            atomicAdd(&g_dx[r * 3 + 0], r0 * coef);
            atomicAdd(&g_dx[r * 3 + 1], r1 * coef);
            atomicAdd(&g_dx[r * 3 + 2], r2 * coef);
        }
    }
}

// ---------------- node update; layer 0 restores zero-invariant -----------
__global__ __launch_bounds__(256) void k_node(const float* __restrict__ nW1,
                                              const float* __restrict__ nb1,
                                              const float* __restrict__ nW2,
                                              const float* __restrict__ nb2,
                                              int N, int resetCsr) {
    __shared__ u64 sN1[128 * 32];
    __shared__ u64 sN2[64 * 32];
    __shared__ u64 snb1[32], snb2[32];
    __shared__ float inb[8][128];
    __shared__ float ub[8][64];
    int tid = threadIdx.x;
    for (int idx = tid; idx < 4096; idx += 256) {
        int i = idx >> 5, j2 = idx & 31;
        sN1[idx] = packxy(nW1[i * 64 + 2 * j2], nW1[i * 64 + 2 * j2 + 1]);
    }
    for (int idx = tid; idx < 2048; idx += 256) {
        int i = idx >> 5, j2 = idx & 31;
        sN2[idx] = packxy(nW2[i * 64 + 2 * j2], nW2[i * 64 + 2 * j2 + 1]);
    }
    if (tid < 32) {
        snb1[tid] = packxy(nb1[2 * tid], nb1[2 * tid + 1]);
        snb2[tid] = packxy(nb2[2 * tid], nb2[2 * tid + 1]);
    }
    __syncthreads();
    int wid = tid >> 5, lane = tid & 31;
    for (int n = blockIdx.x * 8 + wid; n < N; n += gridDim.x * 8) {
        __syncwarp();
        inb[wid][lane]      = g_h[n * 64 + lane];
        inb[wid][lane + 32] = g_h[n * 64 + lane + 32];
        inb[wid][lane + 64] = g_magg[n * 64 + lane];
        inb[wid][lane + 96] = g_magg[n * 64 + lane + 32];
        __syncwarp();
        u64 a0 = snb1[lane], a1 = 0ull, a2 = 0ull, a3 = 0ull;
        #pragma unroll 8
        for (int i = 0; i < 128; i += 4) {
            a0 = fma2(pack2(inb[wid][i]),     sN1[(i)*32 + lane],     a0);
            a1 = fma2(pack2(inb[wid][i + 1]), sN1[(i + 1) * 32 + lane], a1);
            a2 = fma2(pack2(inb[wid][i + 2]), sN1[(i + 2) * 32 + lane], a2);
            a3 = fma2(pack2(inb[wid][i + 3]), sN1[(i + 3) * 32 + lane], a3);
        }
        float2 t = unpack(add2(add2(a0, a1), add2(a2, a3)));
        ub[wid][2 * lane]     = silu(t.x);
        ub[wid][2 * lane + 1] = silu(t.y);
        __syncwarp();
        a0 = snb2[lane]; a1 = 0ull; a2 = 0ull; a3 = 0ull;
        #pragma unroll 8
        for (int i = 0; i < 64; i += 4) {
            a0 = fma2(pack2(ub[wid][i]),     sN2[(i)*32 + lane],     a0);
            a1 = fma2(pack2(ub[wid][i + 1]), sN2[(i + 1) * 32 + lane], a1);
            a2 = fma2(pack2(ub[wid][i + 2]), sN2[(i + 2) * 32 + lane], a2);
            a3 = fma2(pack2(ub[wid][i + 3]), sN2[(i + 3) * 32 + lane], a3);
        }
        float2 dh = unpack(add2(add2(a0, a1), add2(a2, a3)));
        float2* hp = (float2*)(g_h + n * 64);
        float2 hv = hp[lane];
        hv.x += dh.x;
        hv.y += dh.y;
        hp[lane] = hv;
        if (lane < 3) g_x[n * 3 + lane] += g_dx[n * 3 + lane];
        if (resetCsr && lane == 0) { g_hist[n] = 0; g_cur[n] = 0; }
    }
}

// ---------------- final: q per node + batch reductions -------------------
__global__ __launch_bounds__(256) void k_q(const float* __restrict__ qW1,
                                           const float* __restrict__ qb1,
                                           const float* __restrict__ qW2,
                                           const float* __restrict__ qb2,
                                           const int* __restrict__ batch, int N) {
    __shared__ u64 sQ[64 * 32];
    __shared__ u64 sqb[32];
    __shared__ float sw2[64];
    __shared__ float hb[8][64];
    __shared__ float sqb2;
    int tid = threadIdx.x;
    for (int idx = tid; idx < 2048; idx += 256) {
        int i = idx >> 5, j2 = idx & 31;
        sQ[idx] = packxy(qW1[i * 64 + 2 * j2], qW1[i * 64 + 2 * j2 + 1]);
    }
    if (tid < 32) sqb[tid] = packxy(qb1[2 * tid], qb1[2 * tid + 1]);
    if (tid < 64) sw2[tid] = qW2[tid];
    if (tid == 0) sqb2 = qb2[0];
    __syncthreads();
    int wid = tid >> 5, lane = tid & 31;
    for (int n = blockIdx.x * 8 + wid; n < N; n += gridDim.x * 8) {
        __syncwarp();
        hb[wid][lane]      = g_h[n * 64 + lane];
        hb[wid][lane + 32] = g_h[n * 64 + lane + 32];
        __syncwarp();
        u64 a0 = sqb[lane], a1 = 0ull;
        #pragma unroll 8
        for (int i = 0; i < 64; i += 2) {
            a0 = fma2(pack2(hb[wid][i]),     sQ[(i)*32 + lane],     a0);
            a1 = fma2(pack2(hb[wid][i + 1]), sQ[(i + 1) * 32 + lane], a1);
        }
        float2 t = unpack(add2(a0, a1));
        float cd = silu(t.x) * sw2[2 * lane] + silu(t.y) * sw2[2 * lane + 1];
        #pragma unroll
        for (int off = 16; off; off >>= 1) cd += __shfl_xor_sync(0xffffffffu, cd, off);
        if (lane == 0) {
            float q = cd + sqb2;
            int b = batch[n];
            float x0 = g_x[n * 3], x1 = g_x[n * 3 + 1], x2 = g_x[n * 3 + 2];
            atomicAdd(&g_qsum[b], q);
            atomicAdd(&g_qx[b * 3 + 0], q * x0);
            atomicAdd(&g_qx[b * 3 + 1], q * x1);
            atomicAdd(&g_qx[b * 3 + 2], q * x2);
            atomicAdd(&g_xsum[b * 3 + 0], x0);
            atomicAdd(&g_xsum[b * 3 + 1], x1);
            atomicAdd(&g_xsum[b * 3 + 2], x2);
            atomicAdd(&g_cnt[b], 1.0f);
        }
    }
}

__global__ void k_mu(float* __restrict__ out, int B) {
    int b = blockIdx.x * blockDim.x + threadIdx.x;
    if (b < B) {
        float c = fmaxf(g_cnt[b], 1.0f);
        float qs = g_qsum[b];
        #pragma unroll
        for (int k = 0; k < 3; k++) {
            float ctr = g_xsum[b * 3 + k] / c;
            out[b * 3 + k] = g_qx[b * 3 + k] - ctr * qs;
        }
    }
}

// ---------------- launch -------------------------------------------------
extern "C" void kernel_launch(void* const* d_in, const int* in_sizes, int n_in,
                              void* d_out, int out_size) {
    const int*   z    = (const int*)d_in[0];
    const float* pos  = (const float*)d_in[1];
    const int*   ei   = (const int*)d_in[2];
    const int*   bat  = (const int*)d_in[3];
    const float* emb  = (const float*)d_in[4];
    const float* eW1  = (const float*)d_in[5];
    const float* eb1  = (const float*)d_in[6];
    const float* eW2  = (const float*)d_in[7];
    const float* eb2  = (const float*)d_in[8];
    const float* cW   = (const float*)d_in[9];
    const float* cb   = (const float*)d_in[10];
    const float* nW1  = (const float*)d_in[11];
    const float* nb1  = (const float*)d_in[12];
    const float* nW2  = (const float*)d_in[13];
    const float* nb2  = (const float*)d_in[14];
    const float* qW1  = (const float*)d_in[15];
    const float* qb1  = (const float*)d_in[16];
    const float* qW2  = (const float*)d_in[17];
    const float* qb2  = (const float*)d_in[18];
    float* out = (float*)d_out;

    int N = in_sizes[0];
    int E = in_sizes[2] / 2;
    int B = out_size / 3;

    const int esmem = 16384 + 2 * 20096;   // 56576 B
    cudaFuncSetAttribute(k_edge, cudaFuncAttributeMaxDynamicSharedMemorySize, esmem);

    // launch order (2 harness launches precede; ncu captures my 4th = k_edge L0)
    k_inithist<<<(N * 64 + 255) / 256, 256>>>(z, pos, emb, ei, N, B, E);
    k_scan<<<1, 1024>>>(N);

    const int nblk = 1184;
    const int eblk = 444;    // 3 blocks/SM x 256 thr = 24 warps/SM
    const int scatBlocks = (E + 255) / 256;

    k_scatprj<<<scatBlocks + nblk, 256>>>(ei, E, eW1, eb1, N, scatBlocks);
    for (int l = 0; l < 4; l++) {
        if (l > 0) k_proj<<<nblk, 256>>>(eW1 + l * 129 * 64, eb1 + l * 64, N);
        k_edge<<<eblk, 256, esmem>>>(eW1 + l * 129 * 64, eW2 + l * 4096, eb2 + l * 64,
                                     cW + l * 64, cb + l, E);
        k_node<<<nblk, 256>>>(nW1 + l * 128 * 64, nb1 + l * 64, nW2 + l * 4096,
                              nb2 + l * 64, N, l == 0 ? 1 : 0);
    }
    k_q<<<nblk, 256>>>(qW1, qb1, qW2, qb2, bat, N);
    k_mu<<<(B + 255) / 256, 256>>>(out, B);
}

// round 16
// speedup vs baseline: 1.0570x; 1.0570x over previous
#include <cuda_runtime.h>

#define NN 50000
#define EE 1600000
#define BBB 512

// ---------------- device scratch (static; no allocation) ----------------
// ZERO-INVARIANT: g_hist/g_cur zero at load; restored to zero in k_nodefuse L0.
__device__ float g_h[NN * 64];
__device__ float g_x[NN * 3];
__device__ float g_P1[NN * 64];
__device__ float g_P2[NN * 64];
__device__ float g_magg[NN * 64];
__device__ float g_dx[NN * 3];
__device__ int   g_hist[NN];
__device__ int   g_offs[NN + 1];
__device__ int   g_cur[NN];
__device__ int   g_col[EE];
__device__ int   g_row[EE];
__device__ float g_qsum[BBB];
__device__ float g_qx[BBB * 3];
__device__ float g_xsum[BBB * 3];
__device__ float g_cnt[BBB];

typedef unsigned long long u64;

// ---------------- packed f32x2 helpers ----------------------------------
__device__ __forceinline__ u64 fma2(u64 a, u64 b, u64 c) {
    u64 d;
    asm("fma.rn.f32x2 %0, %1, %2, %3;" : "=l"(d) : "l"(a), "l"(b), "l"(c));
    return d;
}
__device__ __forceinline__ u64 add2(u64 a, u64 b) {
    u64 d;
    asm("add.rn.f32x2 %0, %1, %2;" : "=l"(d) : "l"(a), "l"(b));
    return d;
}
__device__ __forceinline__ u64 pack2(float v) {
    u64 d;
    asm("mov.b64 %0, {%1, %1};" : "=l"(d) : "f"(v));
    return d;
}
__device__ __forceinline__ u64 packxy(float x, float y) {
    u64 d;
    asm("mov.b64 %0, {%1, %2};" : "=l"(d) : "f"(x), "f"(y));
    return d;
}
__device__ __forceinline__ float2 unpack(u64 v) {
    float2 f;
    asm("mov.b64 {%0, %1}, %2;" : "=f"(f.x), "=f"(f.y) : "l"(v));
    return f;
}

__device__ __forceinline__ float silu(float v) {
    float e = __expf(-v);
    return __fdividef(v, 1.0f + e);
}

// ---------------- init + edge histogram (zero-invariant g_hist) ----------
__global__ void k_inithist(const int* __restrict__ z, const float* __restrict__ pos,
                           const float* __restrict__ emb, const int* __restrict__ ei,
                           int N, int B, int E) {
    int tid = blockIdx.x * blockDim.x + threadIdx.x;
    if (tid < N * 64) {
        int n = tid >> 6, k = tid & 63;
        g_h[tid] = emb[z[n] * 64 + k];
    }
    if (tid < E) atomicAdd(&g_hist[ei[tid]], 1);
    if (tid < N * 3) g_x[tid] = pos[tid];
    if (tid < B) { g_qsum[tid] = 0.f; g_cnt[tid] = 0.f; }
    if (tid < B * 3) { g_qx[tid] = 0.f; g_xsum[tid] = 0.f; }
}

__global__ void k_scan(int N) {
    __shared__ int ss[1024];
    int tid = threadIdx.x;
    int ch = (N + 1023) / 1024;
    int base = tid * ch;
    int s = 0;
    for (int i = 0; i < ch; i++) {
        int idx = base + i;
        if (idx < N) s += g_hist[idx];
    }
    ss[tid] = s;
    __syncthreads();
    for (int off = 1; off < 1024; off <<= 1) {
        int v = (tid >= off) ? ss[tid - off] : 0;
        __syncthreads();
        ss[tid] += v;
        __syncthreads();
    }
    int run = (tid == 0) ? 0 : ss[tid - 1];
    for (int i = 0; i < ch; i++) {
        int idx = base + i;
        if (idx < N) { g_offs[idx] = run; run += g_hist[idx]; }
    }
    if (tid == 1023) g_offs[N] = ss[1023];
}

// ---------------- scatter + layer-0 proj fused ---------------------------
__device__ __forceinline__ void proj_body(const float* __restrict__ eW1,
                                          const float* __restrict__ eb1,
                                          int N, int bid, int pgrid, int tid) {
    __shared__ u64 sA[64 * 32];
    __shared__ u64 sB[64 * 32];
    __shared__ u64 sb1[32];
    __shared__ __align__(16) float hb[8][64];
    const float* W1a = eW1;
    const float* W1b = eW1 + 64 * 64;
    for (int idx = tid; idx < 2048; idx += 256) {
        int i = idx >> 5, j2 = idx & 31;
        sA[idx] = packxy(W1a[i * 64 + 2 * j2], W1a[i * 64 + 2 * j2 + 1]);
        sB[idx] = packxy(W1b[i * 64 + 2 * j2], W1b[i * 64 + 2 * j2 + 1]);
    }
    if (tid < 32) sb1[tid] = packxy(eb1[2 * tid], eb1[2 * tid + 1]);
    __syncthreads();
    int wid = tid >> 5, lane = tid & 31;
    for (int n = bid * 8 + wid; n < N; n += pgrid * 8) {
        __syncwarp();
        hb[wid][lane]      = g_h[n * 64 + lane];
        hb[wid][lane + 32] = g_h[n * 64 + lane + 32];
        __syncwarp();
        u64 a1a = sb1[lane], a1b = 0ull;
        u64 a2a = 0ull, a2b = 0ull;
        #pragma unroll 8
        for (int i = 0; i < 64; i += 2) {
            u64 v0 = pack2(hb[wid][i]);
            u64 v1 = pack2(hb[wid][i + 1]);
            a1a = fma2(v0, sA[i * 32 + lane], a1a);
            a2a = fma2(v0, sB[i * 32 + lane], a2a);
            a1b = fma2(v1, sA[(i + 1) * 32 + lane], a1b);
            a2b = fma2(v1, sB[(i + 1) * 32 + lane], a2b);
        }
        ((float2*)(g_P1 + n * 64))[lane] = unpack(add2(a1a, a1b));
        ((float2*)(g_P2 + n * 64))[lane] = unpack(add2(a2a, a2b));
        ((float2*)(g_magg + n * 64))[lane] = make_float2(0.f, 0.f);
        if (lane < 3) g_dx[n * 3 + lane] = 0.f;
    }
}

__global__ __launch_bounds__(256) void k_scatprj(const int* __restrict__ ei, int E,
                                                 const float* __restrict__ eW1,
                                                 const float* __restrict__ eb1,
                                                 int N, int scatBlocks) {
    if ((int)blockIdx.x < scatBlocks) {
        int e = blockIdx.x * 256 + threadIdx.x;
        if (e < E) {
            int r = ei[e];
            int idx = g_offs[r] + atomicAdd(&g_cur[r], 1);
            g_col[idx] = ei[E + e];
            g_row[idx] = r;
        }
        return;
    }
    proj_body(eW1, eb1, N, (int)blockIdx.x - scatBlocks,
              (int)gridDim.x - scatBlocks, threadIdx.x);
}

// ---------------- edge kernel (R14 champion, verbatim) -------------------
__global__ __launch_bounds__(256, 3) void k_edge(const float* __restrict__ eW1,
                                                 const float* __restrict__ eW2,
                                                 const float* __restrict__ eb2,
                                                 const float* __restrict__ cW,
                                                 const float* __restrict__ cb, int E) {
    extern __shared__ __align__(16) char dyn[];
    u64* sW2 = (u64*)dyn;
    __shared__ u64 sb2[32];
    __shared__ __align__(16) float swd[64];
    __shared__ float scw[64];
    __shared__ float scb;
    int tid = threadIdx.x;
    for (int idx = tid; idx < 2048; idx += 256) {
        int i = idx >> 5, j2 = idx & 31;
        sW2[idx] = packxy(eW2[i * 64 + 2 * j2], eW2[i * 64 + 2 * j2 + 1]);
    }
    if (tid < 64) { swd[tid] = eW1[128 * 64 + tid]; scw[tid] = cW[tid]; }
    if (tid < 32) sb2[tid] = packxy(eb2[2 * tid], eb2[2 * tid + 1]);
    if (tid == 0) scb = cb[0];
    __syncthreads();
    int wid = tid >> 5, lane = tid & 31;
    int quad = wid >> 2, wq = wid & 3;
    int s = wq & 1, nh = wq >> 1;
    char* qb = dyn + 16384 + quad * 18688;
    float4* tA = (float4*)qb;
    float4* tB = (float4*)(qb + 4352);
    float4* tS = s ? tB : tA;
    float*  msW = (float*)(qb + wq * 4352);
    int*    rows = (int*)(qb + 17408);
    float*  cds  = (float*)(qb + 17664);
    int barid = quad + 1;
    float cbv = scb;
    int ln7 = lane & 7;
    int quadg = blockIdx.x * 2 + quad;
    int nquad = gridDim.x * 2;
    for (int base = quadg * 64; base < E; base += nquad * 64) {
        int e = base + s * 32 + lane;
        bool v = (e < E);
        int ee = v ? e : (E - 1);
        int r = g_row[ee], c = g_col[ee];
        if (wq < 2) rows[s * 32 + lane] = r;
        float r0 = g_x[r * 3]     - g_x[c * 3];
        float r1 = g_x[r * 3 + 1] - g_x[c * 3 + 1];
        float r2 = g_x[r * 3 + 2] - g_x[c * 3 + 2];
        float d2 = r0 * r0 + r1 * r1 + r2 * r2;
        u64 accA[8], accB[8];
        #pragma unroll
        for (int j = 0; j < 8; j++) { accA[j] = sb2[wq * 8 + j]; accB[j] = accA[j]; }
        #pragma unroll
        for (int chunk = 0; chunk < 2; chunk++) {
            #pragma unroll
            for (int i = 0; i < 4; i++) {
                int node = nh * 16 + i * 4 + (lane >> 3);
                int cc = __shfl_sync(0xffffffffu, c, node);
                float4 val = ((const float4*)(g_P2 + cc * 64))[chunk * 8 + ln7];
                tS[node * 8 + (ln7 ^ (node & 7))] = val;
            }
            __syncwarp();
            #pragma unroll
            for (int i = 0; i < 4; i++) {
                int ed = nh * 16 + i * 4 + (lane >> 3);
                int rr = __shfl_sync(0xffffffffu, r, ed);
                float dd = __shfl_sync(0xffffffffu, d2, ed);
                int slot = ed * 8 + (ln7 ^ (ed & 7));
                float4 cv = tS[slot];
                float4 tb = ((const float4*)(g_P1 + rr * 64))[chunk * 8 + ln7];
                float4 wd = ((const float4*)swd)[chunk * 8 + ln7];
                float4 u;
                u.x = silu(tb.x + cv.x + dd * wd.x);
                u.y = silu(tb.y + cv.y + dd * wd.y);
                u.z = silu(tb.z + cv.z + dd * wd.z);
                u.w = silu(tb.w + cv.w + dd * wd.w);
                tS[slot] = u;
            }
            asm volatile("bar.sync %0, %1;" :: "r"(barid), "r"(128) : "memory");
            #pragma unroll
            for (int qq = 0; qq < 8; qq++) {
                int q = chunk * 8 + qq;
                float4 xA = tA[lane * 8 + (qq ^ ln7)];
                float4 xB = tB[lane * 8 + (qq ^ ln7)];
                u64 aA0 = pack2(xA.x), aA1 = pack2(xA.y), aA2 = pack2(xA.z), aA3 = pack2(xA.w);
                u64 aB0 = pack2(xB.x), aB1 = pack2(xB.y), aB2 = pack2(xB.z), aB3 = pack2(xB.w);
                const ulonglong2* wp = (const ulonglong2*)(sW2 + (q * 4) * 32 + wq * 8);
                #pragma unroll
                for (int i = 0; i < 4; i++) {
                    u64 aAi = (i == 0) ? aA0 : (i == 1) ? aA1 : (i == 2) ? aA2 : aA3;
                    u64 aBi = (i == 0) ? aB0 : (i == 1) ? aB1 : (i == 2) ? aB2 : aB3;
                    ulonglong2 b0 = wp[i * 16 + 0];
                    ulonglong2 b1 = wp[i * 16 + 1];
                    ulonglong2 b2 = wp[i * 16 + 2];
                    ulonglong2 b3 = wp[i * 16 + 3];
                    accA[0] = fma2(aAi, b0.x, accA[0]);
                    accB[0] = fma2(aBi, b0.x, accB[0]);
                    accA[1] = fma2(aAi, b0.y, accA[1]);
                    accB[1] = fma2(aBi, b0.y, accB[1]);
                    accA[2] = fma2(aAi, b1.x, accA[2]);
                    accB[2] = fma2(aBi, b1.x, accB[2]);
                    accA[3] = fma2(aAi, b1.y, accA[3]);
                    accB[3] = fma2(aBi, b1.y, accB[3]);
                    accA[4] = fma2(aAi, b2.x, accA[4]);
                    accB[4] = fma2(aBi, b2.x, accB[4]);
                    accA[5] = fma2(aAi, b2.y, accA[5]);
                    accB[5] = fma2(aBi, b2.y, accB[5]);
                    accA[6] = fma2(aAi, b3.x, accA[6]);
                    accB[6] = fma2(aBi, b3.x, accB[6]);
                    accA[7] = fma2(aAi, b3.y, accA[7]);
                    accB[7] = fma2(aBi, b3.y, accB[7]);
                }
            }
            asm volatile("bar.sync %0, %1;" :: "r"(barid), "r"(128) : "memory");
        }
        bool vA = (base + lane) < E;
        bool vB = (base + 32 + lane) < E;
        float cdA = 0.f, cdB = 0.f;
        #pragma unroll
        for (int j = 0; j < 8; j++) {
            int c0 = wq * 16 + 2 * j, c1 = c0 + 1;
            float w0 = scw[c0], w1 = scw[c1];
            float2 mA = unpack(accA[j]);
            float mA0 = vA ? silu(mA.x) : 0.f;
            float mA1 = vA ? silu(mA.y) : 0.f;
            cdA += mA0 * w0 + mA1 * w1;
            msW[(2 * j) * 33 + lane]     = mA0;
            msW[(2 * j + 1) * 33 + lane] = mA1;
            float2 mB = unpack(accB[j]);
            float mB0 = vB ? silu(mB.x) : 0.f;
            float mB1 = vB ? silu(mB.y) : 0.f;
            cdB += mB0 * w0 + mB1 * w1;
            msW[528 + (2 * j) * 33 + lane]     = mB0;
            msW[528 + (2 * j + 1) * 33 + lane] = mB1;
        }
        cds[(0 * 4 + wq) * 32 + lane] = cdA;
        cds[(1 * 4 + wq) * 32 + lane] = cdB;
        __syncwarp();
        {
            int sEl = lane >> 4;
            int chL = lane & 15;
            const float* msS = msW + sEl * 528;
            const int* rowsS = rows + sEl * 32;
            float sum = 0.f;
            #pragma unroll
            for (int e2 = 0; e2 < 32; e2++) {
                sum += msS[chL * 33 + e2];
                int rr = rowsS[e2];
                int rnx = (e2 < 31) ? rowsS[e2 + 1] : -1;
                if (rr != rnx) {
                    atomicAdd(&g_magg[rr * 64 + wq * 16 + chL], sum);
                    sum = 0.f;
                }
            }
        }
        asm volatile("bar.sync %0, %1;" :: "r"(barid), "r"(128) : "memory");
        if (wq < 2 && v) {
            float cd = cbv + cds[(s * 4 + 0) * 32 + lane] + cds[(s * 4 + 1) * 32 + lane]
                           + cds[(s * 4 + 2) * 32 + lane] + cds[(s * 4 + 3) * 32 + lane];
            float coef = tanhf(cd);
            atomicAdd(&g_dx[r * 3 + 0], r0 * coef);
            atomicAdd(&g_dx[r * 3 + 1], r1 * coef);
            atomicAdd(&g_dx[r * 3 + 2], r2 * coef);
        }
    }
}

// ---------------- fused node update + (next proj | q head) ---------------
// mode 0: h' = h + MLP([h,magg]); x += dx; write h'; P1/P2 = proj_{l+1}(h');
//         zero magg/dx for next layer; resetCsr on l==0.
// mode 1: h' as above; x += dx; q = qMLP(h'); batch atomic reductions.
// Dyn smem (u64): sN1 4096 | sN2 2048 | sA 2048 | sB 2048 = 80KB.
__global__ __launch_bounds__(256) void k_nodefuse(
    const float* __restrict__ nW1, const float* __restrict__ nb1,
    const float* __restrict__ nW2, const float* __restrict__ nb2,
    const float* __restrict__ pW1, const float* __restrict__ pb1,
    const float* __restrict__ qW2, const float* __restrict__ qb2,
    const int* __restrict__ batch, int N, int mode, int resetCsr) {
    extern __shared__ u64 dynsm[];
    u64* sN1 = dynsm;
    u64* sN2 = dynsm + 4096;
    u64* sA  = dynsm + 6144;
    u64* sB  = dynsm + 8192;
    __shared__ u64 snb1[32], snb2[32], sb1q[32];
    __shared__ float sw2[64];
    __shared__ float sqb2;
    __shared__ float inb[8][128];
    __shared__ float ub[8][64];
    __shared__ float hnb[8][64];
    __shared__ float xb[8][3];
    int tid = threadIdx.x;
    for (int idx = tid; idx < 4096; idx += 256) {
        int i = idx >> 5, j2 = idx & 31;
        sN1[idx] = packxy(nW1[i * 64 + 2 * j2], nW1[i * 64 + 2 * j2 + 1]);
    }
    for (int idx = tid; idx < 2048; idx += 256) {
        int i = idx >> 5, j2 = idx & 31;
        sN2[idx] = packxy(nW2[i * 64 + 2 * j2], nW2[i * 64 + 2 * j2 + 1]);
        sA[idx]  = packxy(pW1[i * 64 + 2 * j2], pW1[i * 64 + 2 * j2 + 1]);
        if (mode == 0) {
            const float* W1b = pW1 + 64 * 64;
            sB[idx] = packxy(W1b[i * 64 + 2 * j2], W1b[i * 64 + 2 * j2 + 1]);
        }
    }
    if (tid < 32) {
        snb1[tid] = packxy(nb1[2 * tid], nb1[2 * tid + 1]);
        snb2[tid] = packxy(nb2[2 * tid], nb2[2 * tid + 1]);
        sb1q[tid] = packxy(pb1[2 * tid], pb1[2 * tid + 1]);
    }
    if (mode == 1 && tid < 64) sw2[tid] = qW2[tid];
    if (mode == 1 && tid == 0) sqb2 = qb2[0];
    __syncthreads();
    int wid = tid >> 5, lane = tid & 31;
    for (int n = blockIdx.x * 8 + wid; n < N; n += gridDim.x * 8) {
        __syncwarp();
        inb[wid][lane]      = g_h[n * 64 + lane];
        inb[wid][lane + 32] = g_h[n * 64 + lane + 32];
        inb[wid][lane + 64] = g_magg[n * 64 + lane];
        inb[wid][lane + 96] = g_magg[n * 64 + lane + 32];
        if (mode == 0) {
            g_magg[n * 64 + lane] = 0.f;
            g_magg[n * 64 + lane + 32] = 0.f;
        }
        if (lane < 3) {
            float xn = g_x[n * 3 + lane] + g_dx[n * 3 + lane];
            g_x[n * 3 + lane] = xn;
            xb[wid][lane] = xn;
            if (mode == 0) g_dx[n * 3 + lane] = 0.f;
        }
        if (resetCsr && lane == 0) { g_hist[n] = 0; g_cur[n] = 0; }
        __syncwarp();
        u64 a0 = snb1[lane], a1 = 0ull, a2 = 0ull, a3 = 0ull;
        #pragma unroll 8
        for (int i = 0; i < 128; i += 4) {
            a0 = fma2(pack2(inb[wid][i]),     sN1[(i)*32 + lane],     a0);
            a1 = fma2(pack2(inb[wid][i + 1]), sN1[(i + 1) * 32 + lane], a1);
            a2 = fma2(pack2(inb[wid][i + 2]), sN1[(i + 2) * 32 + lane], a2);
            a3 = fma2(pack2(inb[wid][i + 3]), sN1[(i + 3) * 32 + lane], a3);
        }
        float2 t = unpack(add2(add2(a0, a1), add2(a2, a3)));
        ub[wid][2 * lane]     = silu(t.x);
        ub[wid][2 * lane + 1] = silu(t.y);
        __syncwarp();
        a0 = snb2[lane]; a1 = 0ull; a2 = 0ull; a3 = 0ull;
        #pragma unroll 8
        for (int i = 0; i < 64; i += 4) {
            a0 = fma2(pack2(ub[wid][i]),     sN2[(i)*32 + lane],     a0);
            a1 = fma2(pack2(ub[wid][i + 1]), sN2[(i + 1) * 32 + lane], a1);
            a2 = fma2(pack2(ub[wid][i + 2]), sN2[(i + 2) * 32 + lane], a2);
            a3 = fma2(pack2(ub[wid][i + 3]), sN2[(i + 3) * 32 + lane], a3);
        }
        float2 dh = unpack(add2(add2(a0, a1), add2(a2, a3)));
        float h0 = inb[wid][2 * lane]     + dh.x;
        float h1 = inb[wid][2 * lane + 1] + dh.y;
        hnb[wid][2 * lane]     = h0;
        hnb[wid][2 * lane + 1] = h1;
        if (mode == 0) ((float2*)(g_h + n * 64))[lane] = make_float2(h0, h1);
        __syncwarp();
        if (mode == 0) {
            // proj for next layer
            u64 a1a = sb1q[lane], a1b = 0ull;
            u64 a2a = 0ull, a2b = 0ull;
            #pragma unroll 8
            for (int i = 0; i < 64; i += 2) {
                u64 v0 = pack2(hnb[wid][i]);
                u64 v1 = pack2(hnb[wid][i + 1]);
                a1a = fma2(v0, sA[i * 32 + lane], a1a);
                a2a = fma2(v0, sB[i * 32 + lane], a2a);
                a1b = fma2(v1, sA[(i + 1) * 32 + lane], a1b);
                a2b = fma2(v1, sB[(i + 1) * 32 + lane], a2b);
            }
            ((float2*)(g_P1 + n * 64))[lane] = unpack(add2(a1a, a1b));
            ((float2*)(g_P2 + n * 64))[lane] = unpack(add2(a2a, a2b));
        } else {
            // q head
            u64 b0 = sb1q[lane], b1 = 0ull;
            #pragma unroll 8
            for (int i = 0; i < 64; i += 2) {
                b0 = fma2(pack2(hnb[wid][i]),     sA[i * 32 + lane],       b0);
                b1 = fma2(pack2(hnb[wid][i + 1]), sA[(i + 1) * 32 + lane], b1);
            }
            float2 tq = unpack(add2(b0, b1));
            float cd = silu(tq.x) * sw2[2 * lane] + silu(tq.y) * sw2[2 * lane + 1];
            #pragma unroll
            for (int off = 16; off; off >>= 1)
                cd += __shfl_xor_sync(0xffffffffu, cd, off);
            if (lane == 0) {
                float q = cd + sqb2;
                int b = batch[n];
                float x0 = xb[wid][0], x1 = xb[wid][1], x2 = xb[wid][2];
                atomicAdd(&g_qsum[b], q);
                atomicAdd(&g_qx[b * 3 + 0], q * x0);
                atomicAdd(&g_qx[b * 3 + 1], q * x1);
                atomicAdd(&g_qx[b * 3 + 2], q * x2);
                atomicAdd(&g_xsum[b * 3 + 0], x0);
                atomicAdd(&g_xsum[b * 3 + 1], x1);
                atomicAdd(&g_xsum[b * 3 + 2], x2);
                atomicAdd(&g_cnt[b], 1.0f);
            }
        }
    }
}

__global__ void k_mu(float* __restrict__ out, int B) {
    int b = blockIdx.x * blockDim.x + threadIdx.x;
    if (b < B) {
        float c = fmaxf(g_cnt[b], 1.0f);
        float qs = g_qsum[b];
        #pragma unroll
        for (int k = 0; k < 3; k++) {
            float ctr = g_xsum[b * 3 + k] / c;
            out[b * 3 + k] = g_qx[b * 3 + k] - ctr * qs;
        }
    }
}

// ---------------- launch -------------------------------------------------
extern "C" void kernel_launch(void* const* d_in, const int* in_sizes, int n_in,
                              void* d_out, int out_size) {
    const int*   z    = (const int*)d_in[0];
    const float* pos  = (const float*)d_in[1];
    const int*   ei   = (const int*)d_in[2];
    const int*   bat  = (const int*)d_in[3];
    const float* emb  = (const float*)d_in[4];
    const float* eW1  = (const float*)d_in[5];
    const float* eb1  = (const float*)d_in[6];
    const float* eW2  = (const float*)d_in[7];
    const float* eb2  = (const float*)d_in[8];
    const float* cW   = (const float*)d_in[9];
    const float* cb   = (const float*)d_in[10];
    const float* nW1  = (const float*)d_in[11];
    const float* nb1  = (const float*)d_in[12];
    const float* nW2  = (const float*)d_in[13];
    const float* nb2  = (const float*)d_in[14];
    const float* qW1  = (const float*)d_in[15];
    const float* qb1  = (const float*)d_in[16];
    const float* qW2  = (const float*)d_in[17];
    const float* qb2  = (const float*)d_in[18];
    float* out = (float*)d_out;

    int N = in_sizes[0];
    int E = in_sizes[2] / 2;
    int B = out_size / 3;

    const int esmem = 16384 + 2 * 18688;   // 53760 B (R14 k_edge)
    const int fsmem = 10240 * 8;           // 81920 B (k_nodefuse weights)
    cudaFuncSetAttribute(k_edge, cudaFuncAttributeMaxDynamicSharedMemorySize, esmem);
    cudaFuncSetAttribute(k_nodefuse, cudaFuncAttributeMaxDynamicSharedMemorySize, fsmem);

    // launch order (2 harness launches precede; ncu captures my 4th = k_edge L0)
    k_inithist<<<(N * 64 + 255) / 256, 256>>>(z, pos, emb, ei, N, B, E);
    k_scan<<<1, 1024>>>(N);

    const int nblk = 1184;
    const int eblk = 444;
    const int fblk = 296;   // 2 blocks/SM (smem-bound)
    const int scatBlocks = (E + 255) / 256;

    k_scatprj<<<scatBlocks + nblk, 256>>>(ei, E, eW1, eb1, N, scatBlocks);
    for (int l = 0; l < 4; l++) {
        k_edge<<<eblk, 256, esmem>>>(eW1 + l * 129 * 64, eW2 + l * 4096, eb2 + l * 64,
                                     cW + l * 64, cb + l, E);
        if (l < 3) {
            k_nodefuse<<<fblk, 256, fsmem>>>(nW1 + l * 128 * 64, nb1 + l * 64,
                                             nW2 + l * 4096, nb2 + l * 64,
                                             eW1 + (l + 1) * 129 * 64, eb1 + (l + 1) * 64,
                                             qW2, qb2, bat, N, 0, l == 0 ? 1 : 0);
        } else {
            k_nodefuse<<<fblk, 256, fsmem>>>(nW1 + l * 128 * 64, nb1 + l * 64,
                                             nW2 + l * 4096, nb2 + l * 64,
                                             qW1, qb1,
                                             qW2, qb2, bat, N, 1, 0);
        }
    }
    k_mu<<<(B + 255) / 256, 256>>>(out, B);
}

// round 17
// speedup vs baseline: 1.0611x; 1.0039x over previous
#include <cuda_runtime.h>

#define NN 50000
#define EE 1600000
#define BBB 512

// ---------------- device scratch (static; no allocation) ----------------
// ZERO-INVARIANT: g_hist/g_cur zero at load; restored to zero in k_node L0.
__device__ float g_h[NN * 64];
__device__ float g_x[NN * 3];
__device__ float g_P1[NN * 64];
__device__ float g_P2[NN * 64];
__device__ float g_magg[NN * 64];
__device__ float g_dx[NN * 3];
__device__ int   g_hist[NN];
__device__ int   g_offs[NN + 1];
__device__ int   g_cur[NN];
__device__ int   g_col[EE];
__device__ int   g_row[EE];
__device__ float g_qsum[BBB];
__device__ float g_qx[BBB * 3];
__device__ float g_xsum[BBB * 3];
__device__ float g_cnt[BBB];

typedef unsigned long long u64;

// ---------------- packed f32x2 helpers ----------------------------------
__device__ __forceinline__ u64 fma2(u64 a, u64 b, u64 c) {
    u64 d;
    asm("fma.rn.f32x2 %0, %1, %2, %3;" : "=l"(d) : "l"(a), "l"(b), "l"(c));
    return d;
}
__device__ __forceinline__ u64 add2(u64 a, u64 b) {
    u64 d;
    asm("add.rn.f32x2 %0, %1, %2;" : "=l"(d) : "l"(a), "l"(b));
    return d;
}
__device__ __forceinline__ u64 pack2(float v) {
    u64 d;
    asm("mov.b64 %0, {%1, %1};" : "=l"(d) : "f"(v));
    return d;
}
__device__ __forceinline__ u64 packxy(float x, float y) {
    u64 d;
    asm("mov.b64 %0, {%1, %2};" : "=l"(d) : "f"(x), "f"(y));
    return d;
}
__device__ __forceinline__ float2 unpack(u64 v) {
    float2 f;
    asm("mov.b64 {%0, %1}, %2;" : "=f"(f.x), "=f"(f.y) : "l"(v));
    return f;
}

__device__ __forceinline__ float silu(float v) {
    float e = __expf(-v);
    return __fdividef(v, 1.0f + e);
}

// ---------------- init + edge histogram (zero-invariant g_hist) ----------
__global__ void k_inithist(const int* __restrict__ z, const float* __restrict__ pos,
                           const float* __restrict__ emb, const int* __restrict__ ei,
                           int N, int B, int E) {
    int tid = blockIdx.x * blockDim.x + threadIdx.x;
    if (tid < N * 64) {
        int n = tid >> 6, k = tid & 63;
        g_h[tid] = emb[z[n] * 64 + k];
    }
    if (tid < E) atomicAdd(&g_hist[ei[tid]], 1);
    if (tid < N * 3) g_x[tid] = pos[tid];
    if (tid < B) { g_qsum[tid] = 0.f; g_cnt[tid] = 0.f; }
    if (tid < B * 3) { g_qx[tid] = 0.f; g_xsum[tid] = 0.f; }
}

__global__ void k_scan(int N) {
    __shared__ int ss[1024];
    int tid = threadIdx.x;
    int ch = (N + 1023) / 1024;
    int base = tid * ch;
    int s = 0;
    for (int i = 0; i < ch; i++) {
        int idx = base + i;
        if (idx < N) s += g_hist[idx];
    }
    ss[tid] = s;
    __syncthreads();
    for (int off = 1; off < 1024; off <<= 1) {
        int v = (tid >= off) ? ss[tid - off] : 0;
        __syncthreads();
        ss[tid] += v;
        __syncthreads();
    }
    int run = (tid == 0) ? 0 : ss[tid - 1];
    for (int i = 0; i < ch; i++) {
        int idx = base + i;
        if (idx < N) { g_offs[idx] = run; run += g_hist[idx]; }
    }
    if (tid == 1023) g_offs[N] = ss[1023];
}

// ---------------- scatter + layer-0 proj fused ---------------------------
__device__ __forceinline__ void proj_body(const float* __restrict__ eW1,
                                          const float* __restrict__ eb1,
                                          int N, int bid, int pgrid, int tid) {
    __shared__ u64 sA[64 * 32];
    __shared__ u64 sB[64 * 32];
    __shared__ u64 sb1[32];
    __shared__ __align__(16) float hb[8][64];
    const float* W1a = eW1;
    const float* W1b = eW1 + 64 * 64;
    for (int idx = tid; idx < 2048; idx += 256) {
        int i = idx >> 5, j2 = idx & 31;
        sA[idx] = packxy(W1a[i * 64 + 2 * j2], W1a[i * 64 + 2 * j2 + 1]);
        sB[idx] = packxy(W1b[i * 64 + 2 * j2], W1b[i * 64 + 2 * j2 + 1]);
    }
    if (tid < 32) sb1[tid] = packxy(eb1[2 * tid], eb1[2 * tid + 1]);
    __syncthreads();
    int wid = tid >> 5, lane = tid & 31;
    for (int n = bid * 8 + wid; n < N; n += pgrid * 8) {
        __syncwarp();
        hb[wid][lane]      = g_h[n * 64 + lane];
        hb[wid][lane + 32] = g_h[n * 64 + lane + 32];
        __syncwarp();
        u64 a1a = sb1[lane], a1b = 0ull;
        u64 a2a = 0ull, a2b = 0ull;
        #pragma unroll 8
        for (int i = 0; i < 64; i += 2) {
            u64 v0 = pack2(hb[wid][i]);
            u64 v1 = pack2(hb[wid][i + 1]);
            a1a = fma2(v0, sA[i * 32 + lane], a1a);
            a2a = fma2(v0, sB[i * 32 + lane], a2a);
            a1b = fma2(v1, sA[(i + 1) * 32 + lane], a1b);
            a2b = fma2(v1, sB[(i + 1) * 32 + lane], a2b);
        }
        ((float2*)(g_P1 + n * 64))[lane] = unpack(add2(a1a, a1b));
        ((float2*)(g_P2 + n * 64))[lane] = unpack(add2(a2a, a2b));
        ((float2*)(g_magg + n * 64))[lane] = make_float2(0.f, 0.f);
        if (lane < 3) g_dx[n * 3 + lane] = 0.f;
    }
}

__global__ __launch_bounds__(256) void k_scatprj(const int* __restrict__ ei, int E,
                                                 const float* __restrict__ eW1,
                                                 const float* __restrict__ eb1,
                                                 int N, int scatBlocks) {
    if ((int)blockIdx.x < scatBlocks) {
        int e = blockIdx.x * 256 + threadIdx.x;
        if (e < E) {
            int r = ei[e];
            int idx = g_offs[r] + atomicAdd(&g_cur[r], 1);
            g_col[idx] = ei[E + e];
            g_row[idx] = r;
        }
        return;
    }
    proj_body(eW1, eb1, N, (int)blockIdx.x - scatBlocks,
              (int)gridDim.x - scatBlocks, threadIdx.x);
}

__global__ __launch_bounds__(256) void k_proj(const float* __restrict__ eW1,
                                              const float* __restrict__ eb1, int N) {
    proj_body(eW1, eb1, N, (int)blockIdx.x, (int)gridDim.x, threadIdx.x);
}

// ---------------- edge kernel (R14 champion, verbatim) -------------------
__global__ __launch_bounds__(256, 3) void k_edge(const float* __restrict__ eW1,
                                                 const float* __restrict__ eW2,
                                                 const float* __restrict__ eb2,
                                                 const float* __restrict__ cW,
                                                 const float* __restrict__ cb, int E) {
    extern __shared__ __align__(16) char dyn[];
    u64* sW2 = (u64*)dyn;
    __shared__ u64 sb2[32];
    __shared__ __align__(16) float swd[64];
    __shared__ float scw[64];
    __shared__ float scb;
    int tid = threadIdx.x;
    for (int idx = tid; idx < 2048; idx += 256) {
        int i = idx >> 5, j2 = idx & 31;
        sW2[idx] = packxy(eW2[i * 64 + 2 * j2], eW2[i * 64 + 2 * j2 + 1]);
    }
    if (tid < 64) { swd[tid] = eW1[128 * 64 + tid]; scw[tid] = cW[tid]; }
    if (tid < 32) sb2[tid] = packxy(eb2[2 * tid], eb2[2 * tid + 1]);
    if (tid == 0) scb = cb[0];
    __syncthreads();
    int wid = tid >> 5, lane = tid & 31;
    int quad = wid >> 2, wq = wid & 3;
    int s = wq & 1, nh = wq >> 1;
    char* qb = dyn + 16384 + quad * 18688;
    float4* tA = (float4*)qb;
    float4* tB = (float4*)(qb + 4352);
    float4* tS = s ? tB : tA;
    float*  msW = (float*)(qb + wq * 4352);
    int*    rows = (int*)(qb + 17408);
    float*  cds  = (float*)(qb + 17664);
    int barid = quad + 1;
    float cbv = scb;
    int ln7 = lane & 7;
    int quadg = blockIdx.x * 2 + quad;
    int nquad = gridDim.x * 2;
    for (int base = quadg * 64; base < E; base += nquad * 64) {
        int e = base + s * 32 + lane;
        bool v = (e < E);
        int ee = v ? e : (E - 1);
        int r = g_row[ee], c = g_col[ee];
        if (wq < 2) rows[s * 32 + lane] = r;
        float r0 = g_x[r * 3]     - g_x[c * 3];
        float r1 = g_x[r * 3 + 1] - g_x[c * 3 + 1];
        float r2 = g_x[r * 3 + 2] - g_x[c * 3 + 2];
        float d2 = r0 * r0 + r1 * r1 + r2 * r2;
        u64 accA[8], accB[8];
        #pragma unroll
        for (int j = 0; j < 8; j++) { accA[j] = sb2[wq * 8 + j]; accB[j] = accA[j]; }
        #pragma unroll
        for (int chunk = 0; chunk < 2; chunk++) {
            #pragma unroll
            for (int i = 0; i < 4; i++) {
                int node = nh * 16 + i * 4 + (lane >> 3);
                int cc = __shfl_sync(0xffffffffu, c, node);
                float4 val = ((const float4*)(g_P2 + cc * 64))[chunk * 8 + ln7];
                tS[node * 8 + (ln7 ^ (node & 7))] = val;
            }
            __syncwarp();
            #pragma unroll
            for (int i = 0; i < 4; i++) {
                int ed = nh * 16 + i * 4 + (lane >> 3);
                int rr = __shfl_sync(0xffffffffu, r, ed);
                float dd = __shfl_sync(0xffffffffu, d2, ed);
                int slot = ed * 8 + (ln7 ^ (ed & 7));
                float4 cv = tS[slot];
                float4 tb = ((const float4*)(g_P1 + rr * 64))[chunk * 8 + ln7];
                float4 wd = ((const float4*)swd)[chunk * 8 + ln7];
                float4 u;
                u.x = silu(tb.x + cv.x + dd * wd.x);
                u.y = silu(tb.y + cv.y + dd * wd.y);
                u.z = silu(tb.z + cv.z + dd * wd.z);
                u.w = silu(tb.w + cv.w + dd * wd.w);
                tS[slot] = u;
            }
            asm volatile("bar.sync %0, %1;" :: "r"(barid), "r"(128) : "memory");
            #pragma unroll
            for (int qq = 0; qq < 8; qq++) {
                int q = chunk * 8 + qq;
                float4 xA = tA[lane * 8 + (qq ^ ln7)];
                float4 xB = tB[lane * 8 + (qq ^ ln7)];
                u64 aA0 = pack2(xA.x), aA1 = pack2(xA.y), aA2 = pack2(xA.z), aA3 = pack2(xA.w);
                u64 aB0 = pack2(xB.x), aB1 = pack2(xB.y), aB2 = pack2(xB.z), aB3 = pack2(xB.w);
                const ulonglong2* wp = (const ulonglong2*)(sW2 + (q * 4) * 32 + wq * 8);
                #pragma unroll
                for (int i = 0; i < 4; i++) {
                    u64 aAi = (i == 0) ? aA0 : (i == 1) ? aA1 : (i == 2) ? aA2 : aA3;
                    u64 aBi = (i == 0) ? aB0 : (i == 1) ? aB1 : (i == 2) ? aB2 : aB3;
                    ulonglong2 b0 = wp[i * 16 + 0];
                    ulonglong2 b1 = wp[i * 16 + 1];
                    ulonglong2 b2 = wp[i * 16 + 2];
                    ulonglong2 b3 = wp[i * 16 + 3];
                    accA[0] = fma2(aAi, b0.x, accA[0]);
                    accB[0] = fma2(aBi, b0.x, accB[0]);
                    accA[1] = fma2(aAi, b0.y, accA[1]);
                    accB[1] = fma2(aBi, b0.y, accB[1]);
                    accA[2] = fma2(aAi, b1.x, accA[2]);
                    accB[2] = fma2(aBi, b1.x, accB[2]);
                    accA[3] = fma2(aAi, b1.y, accA[3]);
                    accB[3] = fma2(aBi, b1.y, accB[3]);
                    accA[4] = fma2(aAi, b2.x, accA[4]);
                    accB[4] = fma2(aBi, b2.x, accB[4]);
                    accA[5] = fma2(aAi, b2.y, accA[5]);
                    accB[5] = fma2(aBi, b2.y, accB[5]);
                    accA[6] = fma2(aAi, b3.x, accA[6]);
                    accB[6] = fma2(aBi, b3.x, accB[6]);
                    accA[7] = fma2(aAi, b3.y, accA[7]);
                    accB[7] = fma2(aBi, b3.y, accB[7]);
                }
            }
            asm volatile("bar.sync %0, %1;" :: "r"(barid), "r"(128) : "memory");
        }
        bool vA = (base + lane) < E;
        bool vB = (base + 32 + lane) < E;
        float cdA = 0.f, cdB = 0.f;
        #pragma unroll
        for (int j = 0; j < 8; j++) {
            int c0 = wq * 16 + 2 * j, c1 = c0 + 1;
            float w0 = scw[c0], w1 = scw[c1];
            float2 mA = unpack(accA[j]);
            float mA0 = vA ? silu(mA.x) : 0.f;
            float mA1 = vA ? silu(mA.y) : 0.f;
            cdA += mA0 * w0 + mA1 * w1;
            msW[(2 * j) * 33 + lane]     = mA0;
            msW[(2 * j + 1) * 33 + lane] = mA1;
            float2 mB = unpack(accB[j]);
            float mB0 = vB ? silu(mB.x) : 0.f;
            float mB1 = vB ? silu(mB.y) : 0.f;
            cdB += mB0 * w0 + mB1 * w1;
            msW[528 + (2 * j) * 33 + lane]     = mB0;
            msW[528 + (2 * j + 1) * 33 + lane] = mB1;
        }
        cds[(0 * 4 + wq) * 32 + lane] = cdA;
        cds[(1 * 4 + wq) * 32 + lane] = cdB;
        __syncwarp();
        {
            int sEl = lane >> 4;
            int chL = lane & 15;
            const float* msS = msW + sEl * 528;
            const int* rowsS = rows + sEl * 32;
            float sum = 0.f;
            #pragma unroll
            for (int e2 = 0; e2 < 32; e2++) {
                sum += msS[chL * 33 + e2];
                int rr = rowsS[e2];
                int rnx = (e2 < 31) ? rowsS[e2 + 1] : -1;
                if (rr != rnx) {
                    atomicAdd(&g_magg[rr * 64 + wq * 16 + chL], sum);
                    sum = 0.f;
                }
            }
        }
        asm volatile("bar.sync %0, %1;" :: "r"(barid), "r"(128) : "memory");
        if (wq < 2 && v) {
            float cd = cbv + cds[(s * 4 + 0) * 32 + lane] + cds[(s * 4 + 1) * 32 + lane]
                           + cds[(s * 4 + 2) * 32 + lane] + cds[(s * 4 + 3) * 32 + lane];
            float coef = tanhf(cd);
            atomicAdd(&g_dx[r * 3 + 0], r0 * coef);
            atomicAdd(&g_dx[r * 3 + 1], r1 * coef);
            atomicAdd(&g_dx[r * 3 + 2], r2 * coef);
        }
    }
}

// ---------------- node update (+ optional fused q head on last layer) ----
// Dynamic smem: sN1 (4096 u64) | sN2 (2048 u64) | [mode=1: sQ (2048 u64)].
// mode=0 launches use 48KB -> 4 blocks/SM; mode=1 uses 64KB -> 3 blocks/SM.
__global__ __launch_bounds__(256) void k_node(
    const float* __restrict__ nW1, const float* __restrict__ nb1,
    const float* __restrict__ nW2, const float* __restrict__ nb2,
    const float* __restrict__ qW1, const float* __restrict__ qb1,
    const float* __restrict__ qW2, const float* __restrict__ qb2,
    const int* __restrict__ batch, int N, int resetCsr, int mode) {
    extern __shared__ u64 dynsm[];
    u64* sN1 = dynsm;
    u64* sN2 = dynsm + 4096;
    u64* sQ  = dynsm + 6144;
    __shared__ u64 snb1[32], snb2[32], sqb[32];
    __shared__ float sw2[64];
    __shared__ float sqb2;
    __shared__ float inb[8][128];
    __shared__ float ub[8][64];
    __shared__ float xb[8][3];
    int tid = threadIdx.x;
    for (int idx = tid; idx < 4096; idx += 256) {
        int i = idx >> 5, j2 = idx & 31;
        sN1[idx] = packxy(nW1[i * 64 + 2 * j2], nW1[i * 64 + 2 * j2 + 1]);
    }
    for (int idx = tid; idx < 2048; idx += 256) {
        int i = idx >> 5, j2 = idx & 31;
        sN2[idx] = packxy(nW2[i * 64 + 2 * j2], nW2[i * 64 + 2 * j2 + 1]);
    }
    if (mode) {
        for (int idx = tid; idx < 2048; idx += 256) {
            int i = idx >> 5, j2 = idx & 31;
            sQ[idx] = packxy(qW1[i * 64 + 2 * j2], qW1[i * 64 + 2 * j2 + 1]);
        }
        if (tid < 64) sw2[tid] = qW2[tid];
        if (tid < 32) sqb[tid] = packxy(qb1[2 * tid], qb1[2 * tid + 1]);
        if (tid == 0) sqb2 = qb2[0];
    }
    if (tid < 32) {
        snb1[tid] = packxy(nb1[2 * tid], nb1[2 * tid + 1]);
        snb2[tid] = packxy(nb2[2 * tid], nb2[2 * tid + 1]);
    }
    __syncthreads();
    int wid = tid >> 5, lane = tid & 31;
    for (int n = blockIdx.x * 8 + wid; n < N; n += gridDim.x * 8) {
        __syncwarp();
        inb[wid][lane]      = g_h[n * 64 + lane];
        inb[wid][lane + 32] = g_h[n * 64 + lane + 32];
        inb[wid][lane + 64] = g_magg[n * 64 + lane];
        inb[wid][lane + 96] = g_magg[n * 64 + lane + 32];
        if (lane < 3) {
            float xn = g_x[n * 3 + lane] + g_dx[n * 3 + lane];
            g_x[n * 3 + lane] = xn;
            xb[wid][lane] = xn;
        }
        if (resetCsr && lane == 0) { g_hist[n] = 0; g_cur[n] = 0; }
        __syncwarp();
        u64 a0 = snb1[lane], a1 = 0ull, a2 = 0ull, a3 = 0ull;
        #pragma unroll 8
        for (int i = 0; i < 128; i += 4) {
            a0 = fma2(pack2(inb[wid][i]),     sN1[(i)*32 + lane],     a0);
            a1 = fma2(pack2(inb[wid][i + 1]), sN1[(i + 1) * 32 + lane], a1);
            a2 = fma2(pack2(inb[wid][i + 2]), sN1[(i + 2) * 32 + lane], a2);
            a3 = fma2(pack2(inb[wid][i + 3]), sN1[(i + 3) * 32 + lane], a3);
        }
        float2 t = unpack(add2(add2(a0, a1), add2(a2, a3)));
        ub[wid][2 * lane]     = silu(t.x);
        ub[wid][2 * lane + 1] = silu(t.y);
        __syncwarp();
        a0 = snb2[lane]; a1 = 0ull; a2 = 0ull; a3 = 0ull;
        #pragma unroll 8
        for (int i = 0; i < 64; i += 4) {
            a0 = fma2(pack2(ub[wid][i]),     sN2[(i)*32 + lane],     a0);
            a1 = fma2(pack2(ub[wid][i + 1]), sN2[(i + 1) * 32 + lane], a1);
            a2 = fma2(pack2(ub[wid][i + 2]), sN2[(i + 2) * 32 + lane], a2);
            a3 = fma2(pack2(ub[wid][i + 3]), sN2[(i + 3) * 32 + lane], a3);
        }
        float2 dh = unpack(add2(add2(a0, a1), add2(a2, a3)));
        float h0 = inb[wid][2 * lane]     + dh.x;
        float h1 = inb[wid][2 * lane + 1] + dh.y;
        if (!mode) {
            ((float2*)(g_h + n * 64))[lane] = make_float2(h0, h1);
        } else {
            // q head: reuse ub (dead) to hold h'
            __syncwarp();
            ub[wid][2 * lane]     = h0;
            ub[wid][2 * lane + 1] = h1;
            __syncwarp();
            u64 b0 = sqb[lane], b1 = 0ull;
            #pragma unroll 8
            for (int i = 0; i < 64; i += 2) {
                b0 = fma2(pack2(ub[wid][i]),     sQ[i * 32 + lane],       b0);
                b1 = fma2(pack2(ub[wid][i + 1]), sQ[(i + 1) * 32 + lane], b1);
            }
            float2 tq = unpack(add2(b0, b1));
            float cd = silu(tq.x) * sw2[2 * lane] + silu(tq.y) * sw2[2 * lane + 1];
            #pragma unroll
            for (int off = 16; off; off >>= 1)
                cd += __shfl_xor_sync(0xffffffffu, cd, off);
            if (lane == 0) {
                float q = cd + sqb2;
                int b = batch[n];
                float x0 = xb[wid][0], x1 = xb[wid][1], x2 = xb[wid][2];
                atomicAdd(&g_qsum[b], q);
                atomicAdd(&g_qx[b * 3 + 0], q * x0);
                atomicAdd(&g_qx[b * 3 + 1], q * x1);
                atomicAdd(&g_qx[b * 3 + 2], q * x2);
                atomicAdd(&g_xsum[b * 3 + 0], x0);
                atomicAdd(&g_xsum[b * 3 + 1], x1);
                atomicAdd(&g_xsum[b * 3 + 2], x2);
                atomicAdd(&g_cnt[b], 1.0f);
            }
        }
    }
}

__global__ void k_mu(float* __restrict__ out, int B) {
    int b = blockIdx.x * blockDim.x + threadIdx.x;
    if (b < B) {
        float c = fmaxf(g_cnt[b], 1.0f);
        float qs = g_qsum[b];
        #pragma unroll
        for (int k = 0; k < 3; k++) {
            float ctr = g_xsum[b * 3 + k] / c;
            out[b * 3 + k] = g_qx[b * 3 + k] - ctr * qs;
        }
    }
}

// ---------------- launch -------------------------------------------------
extern "C" void kernel_launch(void* const* d_in, const int* in_sizes, int n_in,
                              void* d_out, int out_size) {
    const int*   z    = (const int*)d_in[0];
    const float* pos  = (const float*)d_in[1];
    const int*   ei   = (const int*)d_in[2];
    const int*   bat  = (const int*)d_in[3];
    const float* emb  = (const float*)d_in[4];
    const float* eW1  = (const float*)d_in[5];
    const float* eb1  = (const float*)d_in[6];
    const float* eW2  = (const float*)d_in[7];
    const float* eb2  = (const float*)d_in[8];
    const float* cW   = (const float*)d_in[9];
    const float* cb   = (const float*)d_in[10];
    const float* nW1  = (const float*)d_in[11];
    const float* nb1  = (const float*)d_in[12];
    const float* nW2  = (const float*)d_in[13];
    const float* nb2  = (const float*)d_in[14];
    const float* qW1  = (const float*)d_in[15];
    const float* qb1  = (const float*)d_in[16];
    const float* qW2  = (const float*)d_in[17];
    const float* qb2  = (const float*)d_in[18];
    float* out = (float*)d_out;

    int N = in_sizes[0];
    int E = in_sizes[2] / 2;
    int B = out_size / 3;

    const int esmem = 16384 + 2 * 18688;    // 53760 B (R14 k_edge)
    const int nsm0  = 6144 * 8;             // 49152 B (k_node mode 0)
    const int nsm1  = 8192 * 8;             // 65536 B (k_node mode 1, +q head)
    cudaFuncSetAttribute(k_edge, cudaFuncAttributeMaxDynamicSharedMemorySize, esmem);
    cudaFuncSetAttribute(k_node, cudaFuncAttributeMaxDynamicSharedMemorySize, nsm1);

    // launch order (2 harness launches precede; ncu captures my 4th = k_edge L0)
    k_inithist<<<(N * 64 + 255) / 256, 256>>>(z, pos, emb, ei, N, B, E);
    k_scan<<<1, 1024>>>(N);

    const int nblk = 1184;
    const int eblk = 444;
    const int scatBlocks = (E + 255) / 256;

    k_scatprj<<<scatBlocks + nblk, 256>>>(ei, E, eW1, eb1, N, scatBlocks);
    for (int l = 0; l < 4; l++) {
        if (l > 0) k_proj<<<nblk, 256>>>(eW1 + l * 129 * 64, eb1 + l * 64, N);
        k_edge<<<eblk, 256, esmem>>>(eW1 + l * 129 * 64, eW2 + l * 4096, eb2 + l * 64,
                                     cW + l * 64, cb + l, E);
        int mode = (l == 3) ? 1 : 0;
        k_node<<<nblk, 256, mode ? nsm1 : nsm0>>>(
            nW1 + l * 128 * 64, nb1 + l * 64, nW2 + l * 4096, nb2 + l * 64,
            qW1, qb1, qW2, qb2, bat, N, l == 0 ? 1 : 0, mode);
    }
    k_mu<<<(B + 255) / 256, 256>>>(out, B);
}